// round 9
// baseline (speedup 1.0000x reference)
#include <cuda_runtime.h>
#include <math.h>

// ---------------------------------------------------------------------------
// UncertaintyWeightedLoss — persistent fused kernel, 3-stage cp.async ring.
//   CTA 0,1        : int4 prefix scan of counts -> g_off, release flag
//   CTA [2,2+NB)   : note-MSE partials
//   CTA [2+NB,..)  : persistent CE warps (4/CTA). Meta preloaded one lane per
//                    round (shfl in steady loop). 3-stage per-warp smem ring:
//                    2 stages in flight while 1 is processed (wait_group 2).
//                    Compute reads smem twice (max pass, exp pass) — no big
//                    register buffer. Argmax only when target == max (exact).
//   last CTA       : reduce per-CTA partials, 9 outputs, reset state.
// ---------------------------------------------------------------------------

#define MAXB 16384
#define K4   5                    // float4 slots/lane per stage
#define BUFE 576                  // floats per stage (capacity 576 >= 544)
#define NWARP 4                   // warps per CTA
#define NSTAGE 3
#define NOTE_CHUNK 256
#define MAXCTA 2048
#define L2E 1.4426950408889634f

__device__ int           g_off[2][MAXB];
__device__ double        g_part_ce_s[MAXCTA];
__device__ double        g_part_ce_b[MAXCTA];
__device__ uint2         g_part_cnt[MAXCTA];   // x: nv_s|co_s<<16, y: nv_b|co_b<<16
__device__ double        g_note_sq[(MAXB + NOTE_CHUNK - 1) / NOTE_CHUNK];
__device__ double        g_note_ns[(MAXB + NOTE_CHUNK - 1) / NOTE_CHUNK];
__device__ unsigned int  g_done;
__device__ unsigned int  g_scan_done;

__device__ __forceinline__ float ex2f(float x) {
    float r;
    asm("ex2.approx.f32 %0, %1;" : "=f"(r) : "f"(x));
    return r;
}
__device__ __forceinline__ unsigned int ldacq(const unsigned int* p) {
    unsigned int v;
    asm volatile("ld.acquire.gpu.u32 %0, [%1];" : "=r"(v) : "l"(p) : "memory");
    return v;
}
__device__ __forceinline__ void cpasync16(unsigned int saddr, const void* gaddr) {
    asm volatile("cp.async.cg.shared.global [%0], [%1], 16;"
                 :: "r"(saddr), "l"(gaddr));
}
__device__ __forceinline__ void cpcommit() {
    asm volatile("cp.async.commit_group;");
}
__device__ __forceinline__ void cpwait2() {
    asm volatile("cp.async.wait_group 2;");
}
__device__ __forceinline__ float wmax(float v) {
    #pragma unroll
    for (int o = 16; o; o >>= 1) v = fmaxf(v, __shfl_xor_sync(0xffffffffu, v, o));
    return v;
}
__device__ __forceinline__ float wsum(float v) {
    #pragma unroll
    for (int o = 16; o; o >>= 1) v += __shfl_xor_sync(0xffffffffu, v, o);
    return v;
}
__device__ __forceinline__ int wmin(int v) {
    #pragma unroll
    for (int o = 16; o; o >>= 1) v = min(v, __shfl_xor_sync(0xffffffffu, v, o));
    return v;
}
__device__ __forceinline__ double blk_sum128(double v, double* s) {
    int t = threadIdx.x;
    s[t] = v;
    __syncthreads();
    #pragma unroll
    for (int k = 64; k > 0; k >>= 1) {
        if (t < k) s[t] += s[t + k];
        __syncthreads();
    }
    double r = s[0];
    __syncthreads();
    return r;
}

// prefix scan for one task, 128 threads, int4-vectorized
__device__ void do_scan(const int* __restrict__ counts, int* __restrict__ offs,
                        int Bn, int* wtot) {
    int t = threadIdx.x, lane = t & 31, wid = t >> 5;
    int CH = (Bn + 127) >> 7;
    int base = t * CH;
    bool vec = ((CH & 3) == 0) && (base + CH <= Bn);

    int sum = 0;
    if (vec) {
        const int4* p = (const int4*)(counts + base);
        int q4 = CH >> 2;
        #pragma unroll 4
        for (int q = 0; q < q4; ++q) {
            int4 v = p[q];
            sum += (v.x + v.y) + (v.z + v.w);
        }
    } else {
        for (int k = 0; k < CH; ++k) {
            int idx = base + k;
            if (idx < Bn) sum += counts[idx];
        }
    }
    int incl = sum;
    #pragma unroll
    for (int o = 1; o < 32; o <<= 1) {
        int v = __shfl_up_sync(0xffffffffu, incl, o);
        if (lane >= o) incl += v;
    }
    if (lane == 31) wtot[wid] = incl;
    __syncthreads();
    if (wid == 0 && lane < 4) {
        int v = wtot[lane];
        #pragma unroll
        for (int o = 1; o < 4; o <<= 1) {
            int u = __shfl_up_sync(0x0000000fu, v, o);
            if (lane >= o) v += u;
        }
        wtot[lane] = v;
    }
    __syncthreads();
    int wbase = (wid == 0) ? 0 : wtot[wid - 1];
    int run = wbase + incl - sum;
    if (vec) {
        const int4* p = (const int4*)(counts + base);
        int4* po = (int4*)(offs + base);
        int q4 = CH >> 2;
        #pragma unroll 4
        for (int q = 0; q < q4; ++q) {
            int4 v = p[q];
            int4 o;
            o.x = run; run += v.x;
            o.y = run; run += v.y;
            o.z = run; run += v.z;
            o.w = run; run += v.w;
            po[q] = o;
        }
    } else {
        for (int k = 0; k < CH; ++k) {
            int idx = base + k;
            if (idx < Bn) { offs[idx] = run; run += counts[idx]; }
        }
    }
}

__global__ __launch_bounds__(128, 7) void fused_kernel(
    const float* __restrict__ sys_logits, const float* __restrict__ bar_logits,
    const int* __restrict__ sys_counts,   const int* __restrict__ bar_counts,
    const int* __restrict__ gt_sys,       const int* __restrict__ gt_bar,
    const int* __restrict__ valid,
    const float* __restrict__ notep,      const float* __restrict__ gtnote,
    const float* __restrict__ lv_sys,     const float* __restrict__ lv_bar,
    const float* __restrict__ lv_note,
    int Bn, int note_ctas, int nce, float* __restrict__ out) {

    __shared__ float  ring[NWARP][NSTAGE][BUFE];  // 27.6 KB staging
    __shared__ double sbuf[128];
    __shared__ int    wtot[4];
    __shared__ float  s_ce[2][NWARP];
    __shared__ int    s_nv[2][NWARP], s_co[2][NWARP];
    __shared__ unsigned int ticket;

    int cta = blockIdx.x;
    int t = threadIdx.x;
    const float NEGINF = __int_as_float(0xff800000);
    int ce_base = 2 + note_ctas;

    if (cta < 2) {
        do_scan(cta == 0 ? sys_counts : bar_counts, g_off[cta], Bn, wtot);
        __threadfence();
        __syncthreads();
        if (t == 0) atomicAdd(&g_scan_done, 1u);
    } else if (cta < ce_base) {
        int nb = cta - 2;
        double sq = 0.0, ns = 0.0;
        #pragma unroll
        for (int j = 0; j < NOTE_CHUNK / 128; ++j) {
            int i = nb * NOTE_CHUNK + j * 128 + t;
            if (i < Bn && valid[i] != 0) {
                double d = (double)notep[i] - (double)gtnote[i];
                sq += d * d;
                ns += 1.0;
            }
        }
        sq = blk_sum128(sq, sbuf);
        ns = blk_sum128(ns, sbuf);
        if (t == 0) { g_note_sq[nb] = sq; g_note_ns[nb] = ns; }
    } else {
        // ---------------- persistent 3-stage cp.async CE ----------------
        int lane = t & 31;
        int w = t >> 5;
        int tot = 2 * Bn;
        int stride = nce * NWARP;
        int gw = ((cta - ce_base) * NWARP) | w;

        float ces = 0.0f, ceb = 0.0f;
        int nvs = 0, cos_ = 0, nvb = 0, cob = 0;

        unsigned int shb[NSTAGE];
        #pragma unroll
        for (int p = 0; p < NSTAGE; ++p)
            shb[p] = (unsigned int)__cvta_generic_to_shared(&ring[w][p][0]);

        // ---- prologue: lane r holds round-r meta ----
        int msl = gw + lane * stride;
        int mtask = (msl >= Bn) ? 1 : 0;
        int mb = msl - mtask * Bn;
        int mc = 0, mg = 0, mv = 0, mo = 0;
        bool mok = (msl < tot);
        if (mok) {
            mc = mtask ? bar_counts[mb] : sys_counts[mb];
            mg = mtask ? gt_bar[mb] : gt_sys[mb];
            mv = valid[mb];
        }
        if (t == 0) {
            while (ldacq(&g_scan_done) < 2u) __nanosleep(64);
        }
        __syncthreads();
        if (mok) mo = __ldcg(&g_off[mtask][mb]);

        auto getmeta = [&](int r, int& c, int& o, int& g, int& v) {
            int rr = min(r, 31);
            c = __shfl_sync(0xffffffffu, mc, rr);
            o = __shfl_sync(0xffffffffu, mo, rr);
            g = __shfl_sync(0xffffffffu, mg, rr);
            v = __shfl_sync(0xffffffffu, mv, rr);
        };
        auto issue = [&](int p, int s, int c, int o) {
            if (s < tot && ((o | c) & 3) == 0 && c <= BUFE) {
                const float* ptr = (s >= Bn) ? bar_logits : sys_logits;
                const float4* src = (const float4*)(ptr + o);
                int c4 = c >> 2;
                unsigned int base = shb[p];
                #pragma unroll
                for (int k = 0; k < K4; ++k) {
                    int vi = lane + (k << 5);
                    if (vi < c4) cpasync16(base + vi * 16, src + vi);
                }
            }
            cpcommit();
        };
        auto process = [&](int p, int s, int c, int o, int g, int vld) {
            if (s >= tot) return;
            int task = (s >= Bn) ? 1 : 0;
            float m, Z, tlogit;
            bool cor;
            if (((o | c) & 3) == 0 && c <= BUFE) {
                const float4* sb = (const float4*)&ring[w][p][0];
                int c4 = c >> 2;
                // pass 1: max
                float mymax = NEGINF;
                #pragma unroll
                for (int k = 0; k < K4; ++k) {
                    int vi = lane + (k << 5);
                    if (vi < c4) {
                        float4 v = sb[vi];
                        mymax = fmaxf(fmaxf(fmaxf(mymax, v.x),
                                            fmaxf(v.y, v.z)), v.w);
                    }
                }
                m = wmax(mymax);
                // pass 2: sum of exp
                float a = m * L2E;
                float sm = 0.0f;
                #pragma unroll
                for (int k = 0; k < K4; ++k) {
                    int vi = lane + (k << 5);
                    if (vi < c4) {
                        float4 v = sb[vi];
                        sm += ex2f(fmaf(v.x, L2E, -a))
                            + ex2f(fmaf(v.y, L2E, -a))
                            + ex2f(fmaf(v.z, L2E, -a))
                            + ex2f(fmaf(v.w, L2E, -a));
                    }
                }
                Z = wsum(sm);
                int gi = min(max(g, 0), c > 0 ? c - 1 : 0);
                tlogit = ring[w][p][gi];
                cor = false;
                if (tlogit == m) {                 // rare, warp-uniform
                    int myarg = 0x7fffffff;
                    #pragma unroll
                    for (int k = 0; k < K4; ++k) {
                        int vi = lane + (k << 5);
                        if (vi < c4) {
                            float4 v = sb[vi];
                            int e = vi << 2;
                            if (v.x == m) myarg = min(myarg, e + 0);
                            if (v.y == m) myarg = min(myarg, e + 1);
                            if (v.z == m) myarg = min(myarg, e + 2);
                            if (v.w == m) myarg = min(myarg, e + 3);
                        }
                    }
                    cor = (wmin(myarg) == g);
                }
            } else {
                const float* ptr = task ? bar_logits : sys_logits;
                float mymax = NEGINF;
                for (int i = lane; i < c; i += 32)
                    mymax = fmaxf(mymax, ptr[o + i]);
                m = wmax(mymax);
                float a = m * L2E;
                float sm = 0.0f;
                int myarg = 0x7fffffff;
                for (int i = lane; i < c; i += 32) {
                    float v = ptr[o + i];
                    sm += ex2f(fmaf(v, L2E, -a));
                    if (v == m) myarg = min(myarg, i);
                }
                Z = wsum(sm);
                int arg = wmin(myarg);
                tlogit = (g >= 0 && g < c) ? ptr[o + g] : 0.0f;
                cor = (arg == g);
            }
            if (lane == 0) {
                bool vmask = (c > 0) && (g >= 0) && (g < c) && (vld != 0);
                if (vmask) {
                    float ce = logf(Z) + m - tlogit;
                    int ci = cor ? 1 : 0;
                    if (task) { ceb += ce; nvb += 1; cob += ci; }
                    else      { ces += ce; nvs += 1; cos_ += ci; }
                }
            }
        };

        // ---- 3-deep software pipeline ----
        int sc[NSTAGE], cc[NSTAGE], oo[NSTAGE], gg[NSTAGE], vv[NSTAGE];
        #pragma unroll
        for (int p = 0; p < NSTAGE; ++p) {
            sc[p] = gw + p * stride;
            getmeta(p, cc[p], oo[p], gg[p], vv[p]);
            issue(p, sc[p], cc[p], oo[p]);
        }
        int r = 0;
        while (sc[0] < tot || sc[1] < tot || sc[2] < tot) {
            int p = r % NSTAGE;
            int s = sc[p];
            if (s >= tot) break;
            cpwait2();                         // oldest group done
            process(p, s, cc[p], oo[p], gg[p], vv[p]);
            int sn = s + NSTAGE * stride;
            int cn, on, gn, vn;
            getmeta(r + NSTAGE, cn, on, gn, vn);
            sc[p] = sn; cc[p] = cn; oo[p] = on; gg[p] = gn; vv[p] = vn;
            issue(p, sn, cn, on);
            ++r;
        }

        if (lane == 0) {
            s_ce[0][w] = ces; s_ce[1][w] = ceb;
            s_nv[0][w] = nvs; s_nv[1][w] = nvb;
            s_co[0][w] = cos_; s_co[1][w] = cob;
        }
        __syncthreads();
        if (t == 0) {
            float tce_s = 0.0f, tce_b = 0.0f;
            int tnv_s = 0, tco_s = 0, tnv_b = 0, tco_b = 0;
            #pragma unroll
            for (int i = 0; i < NWARP; ++i) {
                tce_s += s_ce[0][i]; tce_b += s_ce[1][i];
                tnv_s += s_nv[0][i]; tnv_b += s_nv[1][i];
                tco_s += s_co[0][i]; tco_b += s_co[1][i];
            }
            int ci = cta - ce_base;
            g_part_ce_s[ci] = (double)tce_s;
            g_part_ce_b[ci] = (double)tce_b;
            g_part_cnt[ci] = make_uint2(
                (unsigned int)tnv_s | ((unsigned int)tco_s << 16),
                (unsigned int)tnv_b | ((unsigned int)tco_b << 16));
        }
    }

    // ---------------- ticket + last-CTA finalize ----------------
    __syncthreads();
    __threadfence();
    if (t == 0) ticket = atomicAdd(&g_done, 1u);
    __syncthreads();
    if (ticket != gridDim.x - 1) return;

    if (t == 0) { g_done = 0; g_scan_done = 0; }

    double ce_s = 0, ce_b = 0, sq = 0, ns = 0;
    int nv_s = 0, co_s = 0, nv_b = 0, co_b = 0;

    for (int i = t; i < nce; i += 128) {
        ce_s += __ldcg(&g_part_ce_s[i]);
        ce_b += __ldcg(&g_part_ce_b[i]);
        uint2 pc = __ldcg(&g_part_cnt[i]);
        nv_s += pc.x & 0xffff; co_s += pc.x >> 16;
        nv_b += pc.y & 0xffff; co_b += pc.y >> 16;
    }
    for (int i = t; i < note_ctas; i += 128) {
        sq += __ldcg(&g_note_sq[i]);
        ns += __ldcg(&g_note_ns[i]);
    }

    ce_s = blk_sum128(ce_s, sbuf);
    double dnv_s = blk_sum128((double)nv_s, sbuf);
    double dco_s = blk_sum128((double)co_s, sbuf);
    ce_b = blk_sum128(ce_b, sbuf);
    double dnv_b = blk_sum128((double)nv_b, sbuf);
    double dco_b = blk_sum128((double)co_b, sbuf);
    sq = blk_sum128(sq, sbuf);
    ns = blk_sum128(ns, sbuf);

    if (t == 0) {
        double sys_loss  = ce_s / fmax(dnv_s, 1.0);
        double bar_loss  = ce_b / fmax(dnv_b, 1.0);
        double note_loss = (ns > 0.0) ? sq / fmax(ns, 1.0) : 0.0;

        float lvs = lv_sys[0], lvb = lv_bar[0], lvn = lv_note[0];
        float ps = expf(-lvs), pb = expf(-lvb), pn = expf(-lvn);

        double loss = 0.5 * (double)ps * sys_loss + 0.5 * (double)lvs
                    + 0.5 * (double)pb * bar_loss + 0.5 * (double)lvb
                    + 0.5 * (double)pn * note_loss + 0.5 * (double)lvn;

        out[0] = (float)loss;
        out[1] = (float)sys_loss;
        out[2] = (float)bar_loss;
        out[3] = (float)note_loss;
        out[4] = (float)(dco_s / fmax(dnv_s, 1.0));
        out[5] = (float)(dco_b / fmax(dnv_b, 1.0));
        out[6] = ps;
        out[7] = pb;
        out[8] = pn;
    }
}

// ---------------------------------------------------------------------------
extern "C" void kernel_launch(void* const* d_in, const int* in_sizes, int n_in,
                              void* d_out, int out_size) {
    const float* sys_logits = (const float*)d_in[0];
    const int*   sys_counts = (const int*)d_in[1];
    const float* bar_logits = (const float*)d_in[2];
    const int*   bar_counts = (const int*)d_in[3];
    const float* notep      = (const float*)d_in[4];
    const int*   gt_sys     = (const int*)d_in[5];
    const int*   gt_bar     = (const int*)d_in[6];
    const float* gtnote     = (const float*)d_in[7];
    const int*   valid      = (const int*)d_in[8];
    const float* lvs        = (const float*)d_in[9];
    const float* lvb        = (const float*)d_in[10];
    const float* lvn        = (const float*)d_in[11];

    int Bn = in_sizes[1];
    if (Bn > MAXB) Bn = MAXB;

    int note_ctas = (Bn + NOTE_CHUNK - 1) / NOTE_CHUNK;
    int target = 148 * 7;                  // one wave at 7 CTAs/SM
    int nce = target - 2 - note_ctas;      // CE CTAs fit in wave 1 with others
    if (nce < 1) nce = 1;
    if (nce > MAXCTA) nce = MAXCTA;
    // rounds per warp must be <= 32 (meta lanes): 2*MAXB/(nce*4) <= 32 ✓
    int grid = 2 + note_ctas + nce;

    fused_kernel<<<grid, 128>>>(
        sys_logits, bar_logits, sys_counts, bar_counts, gt_sys, gt_bar, valid,
        notep, gtnote, lvs, lvb, lvn, Bn, note_ctas, nce, (float*)d_out);
}